// round 9
// baseline (speedup 1.0000x reference)
#include <cuda_runtime.h>
#include <cuda_fp16.h>

#define NN 50000
#define NE 600000
#define CAP 64            // bucket capacity per node (max degree ~28)

// ---------------- scratch (__device__ globals) -----------------------------
__device__ __half g_Y1h[NN * 64];    // fp16: x @ (diag(w1) Wd1)
__device__ __half g_Y2h[NN * 32];    // fp16: h1 @ (diag(w2) Wd2)
__device__ int    g_deg[NN];
__device__ int    g_bucket[NN * CAP];
__device__ uint2  g_Wfrag1[8 * 8 * 32];   // dense1 B fragments [kt][nt][lane]
__device__ uint2  g_Wfrag2[4 * 4 * 32];   // dense2 B fragments [kt][nt][lane]

__device__ __forceinline__ unsigned s2u(const void* p) {
    return (unsigned)__cvta_generic_to_shared(p);
}
union H2U { __half2 h; unsigned u; };

// ---------------------------------------------------------------------------
// k_setup: zero degrees (blocks 0..195) + build weight fragments (blocks 196+)
// ---------------------------------------------------------------------------
__global__ void k_setup(const float* __restrict__ w1, const float* __restrict__ Wd1,
                        const float* __restrict__ w2, const float* __restrict__ Wd2) {
    int b = blockIdx.x, t = threadIdx.x;
    if (b < 196) {
        int i = b * 256 + t;
        if (i < NN) g_deg[i] = 0;
        return;
    }
    int tid2 = (b - 196) * 256 + t;          // 0..1023
    for (int i = tid2; i < 2048; i += 1024) {
        int lane = i & 31, nt = (i >> 5) & 7, kt = i >> 8;
        int g = lane >> 2, tg = lane & 3;
        int n = nt * 8 + g, k0 = kt * 16 + tg * 2;
        float a0 = Wd1[(k0    ) * 64 + n] * w1[k0    ];
        float a1 = Wd1[(k0 + 1) * 64 + n] * w1[k0 + 1];
        float a2 = Wd1[(k0 + 8) * 64 + n] * w1[k0 + 8];
        float a3 = Wd1[(k0 + 9) * 64 + n] * w1[k0 + 9];
        H2U u0, u1;
        u0.h = __floats2half2_rn(a0, a1);
        u1.h = __floats2half2_rn(a2, a3);
        g_Wfrag1[i] = make_uint2(u0.u, u1.u);
    }
    for (int i = tid2; i < 512; i += 1024) {
        int lane = i & 31, nt = (i >> 5) & 3, kt = i >> 7;
        int g = lane >> 2, tg = lane & 3;
        int n = nt * 8 + g, k0 = kt * 16 + tg * 2;
        float a0 = Wd2[(k0    ) * 32 + n] * w2[k0    ];
        float a1 = Wd2[(k0 + 1) * 32 + n] * w2[k0 + 1];
        float a2 = Wd2[(k0 + 8) * 32 + n] * w2[k0 + 8];
        float a3 = Wd2[(k0 + 9) * 32 + n] * w2[k0 + 9];
        H2U u0, u1;
        u0.h = __floats2half2_rn(a0, a1);
        u1.h = __floats2half2_rn(a2, a3);
        g_Wfrag2[i] = make_uint2(u0.u, u1.u);
    }
}

// ---------------------------------------------------------------------------
// k_fill: one-pass adjacency build. deg doubles as cursor.
// ---------------------------------------------------------------------------
__global__ void k_fill(const int* __restrict__ src, const int* __restrict__ dst) {
    int i = blockIdx.x * 256 + threadIdx.x;
    if (i < NE / 4) {
        int4 s = reinterpret_cast<const int4*>(src)[i];
        int4 d = reinterpret_cast<const int4*>(dst)[i];
        int p;
        p = atomicAdd(&g_deg[d.x], 1); if (p < CAP) g_bucket[d.x * CAP + p] = s.x;
        p = atomicAdd(&g_deg[d.y], 1); if (p < CAP) g_bucket[d.y * CAP + p] = s.y;
        p = atomicAdd(&g_deg[d.z], 1); if (p < CAP) g_bucket[d.z * CAP + p] = s.z;
        p = atomicAdd(&g_deg[d.w], 1); if (p < CAP) g_bucket[d.w * CAP + p] = s.w;
    }
}

// ---------------------------------------------------------------------------
// dense1: Y1 = x @ (diag(w1) Wd1)  (K=128 -> N=64), HMMA, 128-node tiles.
// ---------------------------------------------------------------------------
__global__ void k_dense1(const float* __restrict__ x) {
    __shared__ __half As[128 * 136];     // 34816 B
    int tid = threadIdx.x;
    int node0 = blockIdx.x * 128;
    for (int i = tid; i < 128 * 32; i += 256) {
        int r = i >> 5, c4 = i & 31;
        float4 v = make_float4(0.f, 0.f, 0.f, 0.f);
        if (node0 + r < NN)
            v = *reinterpret_cast<const float4*>(x + (size_t)(node0 + r) * 128 + c4 * 4);
        H2U u0, u1;
        u0.h = __floats2half2_rn(v.x, v.y);
        u1.h = __floats2half2_rn(v.z, v.w);
        *reinterpret_cast<uint2*>(As + r * 136 + c4 * 4) = make_uint2(u0.u, u1.u);
    }
    __syncthreads();

    int w = tid >> 5, lane = tid & 31, g = lane >> 2, tg = lane & 3;
    int warpRow = w * 16;
    int lrow = warpRow + (lane & 15);
    int lkof = (lane >> 4) * 8;

    float acc[8][4] = {};
#pragma unroll
    for (int kt = 0; kt < 8; kt++) {
        unsigned a0, a1, a2, a3;
        unsigned addr = s2u(As + lrow * 136 + kt * 16 + lkof);
        asm volatile("ldmatrix.sync.aligned.m8n8.x4.shared.b16 {%0,%1,%2,%3}, [%4];"
                     : "=r"(a0), "=r"(a1), "=r"(a2), "=r"(a3) : "r"(addr));
#pragma unroll
        for (int nt = 0; nt < 8; nt++) {
            uint2 bb = __ldg(&g_Wfrag1[((kt << 3) + nt) * 32 + lane]);
            asm volatile(
                "mma.sync.aligned.m16n8k16.row.col.f32.f16.f16.f32 "
                "{%0,%1,%2,%3}, {%4,%5,%6,%7}, {%8,%9}, {%0,%1,%2,%3};"
                : "+f"(acc[nt][0]), "+f"(acc[nt][1]), "+f"(acc[nt][2]), "+f"(acc[nt][3])
                : "r"(a0), "r"(a1), "r"(a2), "r"(a3), "r"(bb.x), "r"(bb.y));
        }
    }

    int r0 = node0 + warpRow + g;
    int r1 = r0 + 8;
#pragma unroll
    for (int nt = 0; nt < 8; nt++) {
        int c = nt * 8 + tg * 2;
        if (r0 < NN) {
            H2U u; u.h = __floats2half2_rn(acc[nt][0], acc[nt][1]);
            *reinterpret_cast<unsigned*>(g_Y1h + (size_t)r0 * 64 + c) = u.u;
        }
        if (r1 < NN) {
            H2U u; u.h = __floats2half2_rn(acc[nt][2], acc[nt][3]);
            *reinterpret_cast<unsigned*>(g_Y1h + (size_t)r1 * 64 + c) = u.u;
        }
    }
}

// ---------------------------------------------------------------------------
// half2 accumulation helper
// ---------------------------------------------------------------------------
__device__ __forceinline__ void hacc(__half2 a[4], uint4 v) {
    __half2* h = reinterpret_cast<__half2*>(&v);
    a[0] = __hadd2(a[0], h[0]);
    a[1] = __hadd2(a[1], h[1]);
    a[2] = __hadd2(a[2], h[2]);
    a[3] = __hadd2(a[3], h[3]);
}

// ---------------------------------------------------------------------------
// k_gd2: FUSED gather1 + dense2.
// Phase A: gather h1 rows (A@Y1 + b1) for this 128-node tile directly into
//          the smem A-tile (fp16).  8 warps x 4 subs x 4 rounds = 128 rows.
// Phase B: HMMA  Y2 = h1_tile @ (diag(w2) Wd2)  -> g_Y2h.
// ---------------------------------------------------------------------------
__global__ void k_gd2(const float* __restrict__ b1) {
    __shared__ __half As[128 * 72];      // 18432 B
    int tid = threadIdx.x;
    int node0 = blockIdx.x * 128;
    int w = tid >> 5, lane = tid & 31;

    // ---- Phase A: gather into smem
    {
        int sub = lane >> 3, sl = lane & 7;
        float4 bL = __ldg(reinterpret_cast<const float4*>(b1 + sl * 8));
        float4 bH = __ldg(reinterpret_cast<const float4*>(b1 + sl * 8 + 4));
#pragma unroll
        for (int round = 0; round < 4; round++) {
            int r = w * 16 + round * 4 + sub;     // 0..127
            int node = node0 + r;
            __half2 z = __float2half2_rn(0.f);
            __half2 s0[4] = {z, z, z, z}, s1[4] = {z, z, z, z};
            __half2 s2[4] = {z, z, z, z}, s3[4] = {z, z, z, z};
            if (node < NN) {
                int n = g_deg[node]; if (n > CAP) n = CAP;
                const int* bkt = g_bucket + (size_t)node * CAP;
                int j = 0;
                for (; j + 4 <= n; j += 4) {
                    int4 idx = *reinterpret_cast<const int4*>(bkt + j);
                    hacc(s0, *reinterpret_cast<const uint4*>(g_Y1h + (size_t)idx.x * 64 + sl * 8));
                    hacc(s1, *reinterpret_cast<const uint4*>(g_Y1h + (size_t)idx.y * 64 + sl * 8));
                    hacc(s2, *reinterpret_cast<const uint4*>(g_Y1h + (size_t)idx.z * 64 + sl * 8));
                    hacc(s3, *reinterpret_cast<const uint4*>(g_Y1h + (size_t)idx.w * 64 + sl * 8));
                }
                for (; j < n; j++)
                    hacc(s0, *reinterpret_cast<const uint4*>(g_Y1h + (size_t)bkt[j] * 64 + sl * 8));
            }
            // merge slots in fp32, add bias, pack to fp16 smem
            float2 f0 = __half22float2(s0[0]);
            { float2 t = __half22float2(s1[0]); f0.x += t.x; f0.y += t.y; }
            { float2 t = __half22float2(s2[0]); f0.x += t.x; f0.y += t.y; }
            { float2 t = __half22float2(s3[0]); f0.x += t.x; f0.y += t.y; }
            float2 f1 = __half22float2(s0[1]);
            { float2 t = __half22float2(s1[1]); f1.x += t.x; f1.y += t.y; }
            { float2 t = __half22float2(s2[1]); f1.x += t.x; f1.y += t.y; }
            { float2 t = __half22float2(s3[1]); f1.x += t.x; f1.y += t.y; }
            float2 f2 = __half22float2(s0[2]);
            { float2 t = __half22float2(s1[2]); f2.x += t.x; f2.y += t.y; }
            { float2 t = __half22float2(s2[2]); f2.x += t.x; f2.y += t.y; }
            { float2 t = __half22float2(s3[2]); f2.x += t.x; f2.y += t.y; }
            float2 f3 = __half22float2(s0[3]);
            { float2 t = __half22float2(s1[3]); f3.x += t.x; f3.y += t.y; }
            { float2 t = __half22float2(s2[3]); f3.x += t.x; f3.y += t.y; }
            { float2 t = __half22float2(s3[3]); f3.x += t.x; f3.y += t.y; }

            H2U p0, p1, p2, p3;
            p0.h = __floats2half2_rn(f0.x + bL.x, f0.y + bL.y);
            p1.h = __floats2half2_rn(f1.x + bL.z, f1.y + bL.w);
            p2.h = __floats2half2_rn(f2.x + bH.x, f2.y + bH.y);
            p3.h = __floats2half2_rn(f3.x + bH.z, f3.y + bH.w);
            *reinterpret_cast<uint4*>(As + r * 72 + sl * 8) =
                make_uint4(p0.u, p1.u, p2.u, p3.u);
        }
    }
    __syncthreads();

    // ---- Phase B: HMMA (K=64 -> N=32)
    int g = lane >> 2, tg = lane & 3;
    int warpRow = w * 16;
    int lrow = warpRow + (lane & 15);
    int lkof = (lane >> 4) * 8;

    float acc[4][4] = {};
#pragma unroll
    for (int kt = 0; kt < 4; kt++) {
        unsigned a0, a1, a2, a3;
        unsigned addr = s2u(As + lrow * 72 + kt * 16 + lkof);
        asm volatile("ldmatrix.sync.aligned.m8n8.x4.shared.b16 {%0,%1,%2,%3}, [%4];"
                     : "=r"(a0), "=r"(a1), "=r"(a2), "=r"(a3) : "r"(addr));
#pragma unroll
        for (int nt = 0; nt < 4; nt++) {
            uint2 bb = __ldg(&g_Wfrag2[((kt << 2) + nt) * 32 + lane]);
            asm volatile(
                "mma.sync.aligned.m16n8k16.row.col.f32.f16.f16.f32 "
                "{%0,%1,%2,%3}, {%4,%5,%6,%7}, {%8,%9}, {%0,%1,%2,%3};"
                : "+f"(acc[nt][0]), "+f"(acc[nt][1]), "+f"(acc[nt][2]), "+f"(acc[nt][3])
                : "r"(a0), "r"(a1), "r"(a2), "r"(a3), "r"(bb.x), "r"(bb.y));
        }
    }

    int r0 = node0 + warpRow + g;
    int r1 = r0 + 8;
#pragma unroll
    for (int nt = 0; nt < 4; nt++) {
        int c = nt * 8 + tg * 2;
        if (r0 < NN) {
            H2U u; u.h = __floats2half2_rn(acc[nt][0], acc[nt][1]);
            *reinterpret_cast<unsigned*>(g_Y2h + (size_t)r0 * 32 + c) = u.u;
        }
        if (r1 < NN) {
            H2U u; u.h = __floats2half2_rn(acc[nt][2], acc[nt][3]);
            *reinterpret_cast<unsigned*>(g_Y2h + (size_t)r1 * 32 + c) = u.u;
        }
    }
}

// ---------------------------------------------------------------------------
// gather2 + head + softmax.  8 nodes/warp, 4 lanes x 8 halves.
// ---------------------------------------------------------------------------
__global__ void k_gather2_final(const float* __restrict__ b2,
                                const float* __restrict__ Wout,
                                const float* __restrict__ bout,
                                float* __restrict__ out) {
    int gw = (blockIdx.x * 256 + threadIdx.x) >> 5;
    int lane = threadIdx.x & 31;
    int sub = lane >> 2, sl = lane & 3;
    int node = gw * 8 + sub;
    if (node >= NN) return;

    int n = g_deg[node]; if (n > CAP) n = CAP;
    const int* bkt = g_bucket + (size_t)node * CAP;
    __half2 z = __float2half2_rn(0.f);
    __half2 s0[4] = {z, z, z, z}, s1[4] = {z, z, z, z};
    __half2 s2[4] = {z, z, z, z}, s3[4] = {z, z, z, z};

    int j = 0;
    for (; j + 4 <= n; j += 4) {
        int4 idx = *reinterpret_cast<const int4*>(bkt + j);
        hacc(s0, *reinterpret_cast<const uint4*>(g_Y2h + (size_t)idx.x * 32 + sl * 8));
        hacc(s1, *reinterpret_cast<const uint4*>(g_Y2h + (size_t)idx.y * 32 + sl * 8));
        hacc(s2, *reinterpret_cast<const uint4*>(g_Y2h + (size_t)idx.z * 32 + sl * 8));
        hacc(s3, *reinterpret_cast<const uint4*>(g_Y2h + (size_t)idx.w * 32 + sl * 8));
    }
    for (; j < n; j++)
        hacc(s0, *reinterpret_cast<const uint4*>(g_Y2h + (size_t)bkt[j] * 32 + sl * 8));

    float4 bL = __ldg(reinterpret_cast<const float4*>(b2 + sl * 8));
    float4 bH = __ldg(reinterpret_cast<const float4*>(b2 + sl * 8 + 4));
    float h[8];
#pragma unroll
    for (int q = 0; q < 4; q++) {
        float2 f  = __half22float2(s0[q]);
        float2 t1 = __half22float2(s1[q]);
        float2 t2 = __half22float2(s2[q]);
        float2 t3 = __half22float2(s3[q]);
        h[q * 2]     = f.x + t1.x + t2.x + t3.x;
        h[q * 2 + 1] = f.y + t1.y + t2.y + t3.y;
    }
    h[0] += bL.x; h[1] += bL.y; h[2] += bL.z; h[3] += bL.w;
    h[4] += bH.x; h[5] += bH.y; h[6] += bH.z; h[7] += bH.w;

    float lg[4];
#pragma unroll
    for (int c = 0; c < 4; c++) {
        float ps = 0.f;
#pragma unroll
        for (int k = 0; k < 8; k++)
            ps = fmaf(h[k], __ldg(Wout + (sl * 8 + k) * 4 + c), ps);
        ps += __shfl_xor_sync(0xffffffffu, ps, 1);
        ps += __shfl_xor_sync(0xffffffffu, ps, 2);
        lg[c] = ps + __ldg(bout + c);
    }

    float m = fmaxf(fmaxf(lg[0], lg[1]), fmaxf(lg[2], lg[3]));
    float e0 = __expf(lg[0] - m);
    float e1 = __expf(lg[1] - m);
    float e2 = __expf(lg[2] - m);
    float e3 = __expf(lg[3] - m);
    float inv = 1.0f / (e0 + e1 + e2 + e3);
    if (sl == 0)
        *reinterpret_cast<float4*>(out + (size_t)node * 4) =
            make_float4(e0 * inv, e1 * inv, e2 * inv, e3 * inv);
}

// ---------------------------------------------------------------------------
// Launch.  Inputs: x, src, dst, w1, Wd1, b1, w2, Wd2, b2, Wout, bout
// ---------------------------------------------------------------------------
extern "C" void kernel_launch(void* const* d_in, const int* in_sizes, int n_in,
                              void* d_out, int out_size) {
    const float* x    = (const float*)d_in[0];
    const int*   src  = (const int*)  d_in[1];
    const int*   dst  = (const int*)  d_in[2];
    const float* w1   = (const float*)d_in[3];
    const float* Wd1  = (const float*)d_in[4];
    const float* b1   = (const float*)d_in[5];
    const float* w2   = (const float*)d_in[6];
    const float* Wd2  = (const float*)d_in[7];
    const float* b2   = (const float*)d_in[8];
    const float* Wout = (const float*)d_in[9];
    const float* bout = (const float*)d_in[10];
    float* out = (float*)d_out;

    k_setup<<<200, 256>>>(w1, Wd1, w2, Wd2);            // deg=0 + B fragments
    k_fill<<<586, 256>>>(src, dst);                     // adjacency buckets
    k_dense1<<<391, 256>>>(x);                          // Y1 (HMMA)
    k_gd2<<<391, 256>>>(b1);                            // fused gather1+dense2
    k_gather2_final<<<782, 256>>>(b2, Wout, bout, out); // gather2 + head
}

// round 10
// speedup vs baseline: 1.1287x; 1.1287x over previous
#include <cuda_runtime.h>
#include <cuda_fp16.h>

#define NN 50000
#define NE 600000
#define CAP 64            // bucket capacity per node (max degree ~28)

// ---------------- scratch (__device__ globals) -----------------------------
__device__ __half g_Y1h[NN * 64];    // fp16: x @ (diag(w1) Wd1)
__device__ __half g_h1h[NN * 64];    // fp16: A @ Y1 + b1
__device__ __half g_Y2h[NN * 32];    // fp16: h1 @ (diag(w2) Wd2)
__device__ int    g_deg[NN];
__device__ int    g_bucket[NN * CAP];
__device__ uint2  g_Wfrag1[8 * 8 * 32];   // dense1 B fragments [kt][nt][lane]
__device__ uint2  g_Wfrag2[4 * 4 * 32];   // dense2 B fragments [kt][nt][lane]

__device__ __forceinline__ unsigned s2u(const void* p) {
    return (unsigned)__cvta_generic_to_shared(p);
}
union H2U { __half2 h; unsigned u; };

// ---------------------------------------------------------------------------
__global__ void k_zero() {
    int i = blockIdx.x * 256 + threadIdx.x;
    if (i < NN) g_deg[i] = 0;
}

// ---------------------------------------------------------------------------
// k_wfrag: build pre-folded fp16 MMA B-fragments for both dense layers.
// ---------------------------------------------------------------------------
__global__ void k_wfrag(const float* __restrict__ w1, const float* __restrict__ Wd1,
                        const float* __restrict__ w2, const float* __restrict__ Wd2) {
    int tid2 = blockIdx.x * 256 + threadIdx.x;     // 0..1023
    for (int i = tid2; i < 2048; i += 1024) {
        int lane = i & 31, nt = (i >> 5) & 7, kt = i >> 8;
        int g = lane >> 2, tg = lane & 3;
        int n = nt * 8 + g, k0 = kt * 16 + tg * 2;
        float a0 = Wd1[(k0    ) * 64 + n] * w1[k0    ];
        float a1 = Wd1[(k0 + 1) * 64 + n] * w1[k0 + 1];
        float a2 = Wd1[(k0 + 8) * 64 + n] * w1[k0 + 8];
        float a3 = Wd1[(k0 + 9) * 64 + n] * w1[k0 + 9];
        H2U u0, u1;
        u0.h = __floats2half2_rn(a0, a1);
        u1.h = __floats2half2_rn(a2, a3);
        g_Wfrag1[i] = make_uint2(u0.u, u1.u);
    }
    for (int i = tid2; i < 512; i += 1024) {
        int lane = i & 31, nt = (i >> 5) & 3, kt = i >> 7;
        int g = lane >> 2, tg = lane & 3;
        int n = nt * 8 + g, k0 = kt * 16 + tg * 2;
        float a0 = Wd2[(k0    ) * 32 + n] * w2[k0    ];
        float a1 = Wd2[(k0 + 1) * 32 + n] * w2[k0 + 1];
        float a2 = Wd2[(k0 + 8) * 32 + n] * w2[k0 + 8];
        float a3 = Wd2[(k0 + 9) * 32 + n] * w2[k0 + 9];
        H2U u0, u1;
        u0.h = __floats2half2_rn(a0, a1);
        u1.h = __floats2half2_rn(a2, a3);
        g_Wfrag2[i] = make_uint2(u0.u, u1.u);
    }
}

// ---------------------------------------------------------------------------
// k_fill: one-pass adjacency build. deg doubles as cursor.
// ---------------------------------------------------------------------------
__global__ void k_fill(const int* __restrict__ src, const int* __restrict__ dst) {
    int i = blockIdx.x * 256 + threadIdx.x;
    if (i < NE / 4) {
        int4 s = reinterpret_cast<const int4*>(src)[i];
        int4 d = reinterpret_cast<const int4*>(dst)[i];
        int p;
        p = atomicAdd(&g_deg[d.x], 1); if (p < CAP) g_bucket[d.x * CAP + p] = s.x;
        p = atomicAdd(&g_deg[d.y], 1); if (p < CAP) g_bucket[d.y * CAP + p] = s.y;
        p = atomicAdd(&g_deg[d.z], 1); if (p < CAP) g_bucket[d.z * CAP + p] = s.z;
        p = atomicAdd(&g_deg[d.w], 1); if (p < CAP) g_bucket[d.w * CAP + p] = s.w;
    }
}

// ---------------------------------------------------------------------------
// dense1: Y1 = x @ (diag(w1) Wd1)  (K=128 -> N=64), HMMA, 128-node tiles.
// ---------------------------------------------------------------------------
__global__ void k_dense1(const float* __restrict__ x) {
    __shared__ __half As[128 * 136];     // 34816 B
    int tid = threadIdx.x;
    int node0 = blockIdx.x * 128;
    for (int i = tid; i < 128 * 32; i += 256) {
        int r = i >> 5, c4 = i & 31;
        float4 v = make_float4(0.f, 0.f, 0.f, 0.f);
        if (node0 + r < NN)
            v = *reinterpret_cast<const float4*>(x + (size_t)(node0 + r) * 128 + c4 * 4);
        H2U u0, u1;
        u0.h = __floats2half2_rn(v.x, v.y);
        u1.h = __floats2half2_rn(v.z, v.w);
        *reinterpret_cast<uint2*>(As + r * 136 + c4 * 4) = make_uint2(u0.u, u1.u);
    }
    __syncthreads();

    int w = tid >> 5, lane = tid & 31, g = lane >> 2, tg = lane & 3;
    int warpRow = w * 16;
    int lrow = warpRow + (lane & 15);
    int lkof = (lane >> 4) * 8;

    float acc[8][4] = {};
#pragma unroll
    for (int kt = 0; kt < 8; kt++) {
        unsigned a0, a1, a2, a3;
        unsigned addr = s2u(As + lrow * 136 + kt * 16 + lkof);
        asm volatile("ldmatrix.sync.aligned.m8n8.x4.shared.b16 {%0,%1,%2,%3}, [%4];"
                     : "=r"(a0), "=r"(a1), "=r"(a2), "=r"(a3) : "r"(addr));
#pragma unroll
        for (int nt = 0; nt < 8; nt++) {
            uint2 bb = __ldg(&g_Wfrag1[((kt << 3) + nt) * 32 + lane]);
            asm volatile(
                "mma.sync.aligned.m16n8k16.row.col.f32.f16.f16.f32 "
                "{%0,%1,%2,%3}, {%4,%5,%6,%7}, {%8,%9}, {%0,%1,%2,%3};"
                : "+f"(acc[nt][0]), "+f"(acc[nt][1]), "+f"(acc[nt][2]), "+f"(acc[nt][3])
                : "r"(a0), "r"(a1), "r"(a2), "r"(a3), "r"(bb.x), "r"(bb.y));
        }
    }

    int r0 = node0 + warpRow + g;
    int r1 = r0 + 8;
#pragma unroll
    for (int nt = 0; nt < 8; nt++) {
        int c = nt * 8 + tg * 2;
        if (r0 < NN) {
            H2U u; u.h = __floats2half2_rn(acc[nt][0], acc[nt][1]);
            *reinterpret_cast<unsigned*>(g_Y1h + (size_t)r0 * 64 + c) = u.u;
        }
        if (r1 < NN) {
            H2U u; u.h = __floats2half2_rn(acc[nt][2], acc[nt][3]);
            *reinterpret_cast<unsigned*>(g_Y1h + (size_t)r1 * 64 + c) = u.u;
        }
    }
}

// ---------------------------------------------------------------------------
// half2 accumulation helper
// ---------------------------------------------------------------------------
__device__ __forceinline__ void hacc(__half2 a[4], uint4 v) {
    __half2* h = reinterpret_cast<__half2*>(&v);
    a[0] = __hadd2(a[0], h[0]);
    a[1] = __hadd2(a[1], h[1]);
    a[2] = __hadd2(a[2], h[2]);
    a[3] = __hadd2(a[3], h[3]);
}

// ---------------------------------------------------------------------------
// gather1: h1 = A@Y1 + b1, fp16 out. 4 nodes/warp, 8 lanes x 8 halves.
// ---------------------------------------------------------------------------
__global__ void k_gather1(const float* __restrict__ b1) {
    int gw = (blockIdx.x * 256 + threadIdx.x) >> 5;
    int lane = threadIdx.x & 31;
    int sub = lane >> 3, sl = lane & 7;
    int node = gw * 4 + sub;
    if (node >= NN) return;

    int n = g_deg[node]; if (n > CAP) n = CAP;
    const int* bkt = g_bucket + (size_t)node * CAP;
    __half2 z = __float2half2_rn(0.f);
    __half2 s0[4] = {z, z, z, z}, s1[4] = {z, z, z, z};
    __half2 s2[4] = {z, z, z, z}, s3[4] = {z, z, z, z};

    int j = 0;
    for (; j + 4 <= n; j += 4) {
        int4 idx = *reinterpret_cast<const int4*>(bkt + j);
        hacc(s0, *reinterpret_cast<const uint4*>(g_Y1h + (size_t)idx.x * 64 + sl * 8));
        hacc(s1, *reinterpret_cast<const uint4*>(g_Y1h + (size_t)idx.y * 64 + sl * 8));
        hacc(s2, *reinterpret_cast<const uint4*>(g_Y1h + (size_t)idx.z * 64 + sl * 8));
        hacc(s3, *reinterpret_cast<const uint4*>(g_Y1h + (size_t)idx.w * 64 + sl * 8));
    }
    for (; j < n; j++)
        hacc(s0, *reinterpret_cast<const uint4*>(g_Y1h + (size_t)bkt[j] * 64 + sl * 8));

    float4 bL = __ldg(reinterpret_cast<const float4*>(b1 + sl * 8));
    float4 bH = __ldg(reinterpret_cast<const float4*>(b1 + sl * 8 + 4));
    float2 f0, f1, f2, f3;
    f0 = __half22float2(s0[0]); { float2 t = __half22float2(s1[0]); f0.x += t.x; f0.y += t.y; }
    { float2 t = __half22float2(s2[0]); f0.x += t.x; f0.y += t.y; }
    { float2 t = __half22float2(s3[0]); f0.x += t.x; f0.y += t.y; }
    f1 = __half22float2(s0[1]); { float2 t = __half22float2(s1[1]); f1.x += t.x; f1.y += t.y; }
    { float2 t = __half22float2(s2[1]); f1.x += t.x; f1.y += t.y; }
    { float2 t = __half22float2(s3[1]); f1.x += t.x; f1.y += t.y; }
    f2 = __half22float2(s0[2]); { float2 t = __half22float2(s1[2]); f2.x += t.x; f2.y += t.y; }
    { float2 t = __half22float2(s2[2]); f2.x += t.x; f2.y += t.y; }
    { float2 t = __half22float2(s3[2]); f2.x += t.x; f2.y += t.y; }
    f3 = __half22float2(s0[3]); { float2 t = __half22float2(s1[3]); f3.x += t.x; f3.y += t.y; }
    { float2 t = __half22float2(s2[3]); f3.x += t.x; f3.y += t.y; }
    { float2 t = __half22float2(s3[3]); f3.x += t.x; f3.y += t.y; }

    H2U p0, p1, p2, p3;
    p0.h = __floats2half2_rn(f0.x + bL.x, f0.y + bL.y);
    p1.h = __floats2half2_rn(f1.x + bL.z, f1.y + bL.w);
    p2.h = __floats2half2_rn(f2.x + bH.x, f2.y + bH.y);
    p3.h = __floats2half2_rn(f3.x + bH.z, f3.y + bH.w);
    *reinterpret_cast<uint4*>(g_h1h + (size_t)node * 64 + sl * 8) =
        make_uint4(p0.u, p1.u, p2.u, p3.u);
}

// ---------------------------------------------------------------------------
// dense2: Y2 = h1 @ (diag(w2) Wd2)  (K=64 -> N=32), HMMA, 128-node tiles.
// ---------------------------------------------------------------------------
__global__ void k_dense2() {
    __shared__ __half As[128 * 72];      // 18432 B
    int tid = threadIdx.x;
    int node0 = blockIdx.x * 128;
    for (int i = tid; i < 128 * 8; i += 256) {
        int r = i >> 3, q = i & 7;
        uint4 v = make_uint4(0u, 0u, 0u, 0u);
        if (node0 + r < NN)
            v = *reinterpret_cast<const uint4*>(g_h1h + (size_t)(node0 + r) * 64 + q * 8);
        *reinterpret_cast<uint4*>(As + r * 72 + q * 8) = v;
    }
    __syncthreads();

    int w = tid >> 5, lane = tid & 31, g = lane >> 2, tg = lane & 3;
    int warpRow = w * 16;
    int lrow = warpRow + (lane & 15);
    int lkof = (lane >> 4) * 8;

    float acc[4][4] = {};
#pragma unroll
    for (int kt = 0; kt < 4; kt++) {
        unsigned a0, a1, a2, a3;
        unsigned addr = s2u(As + lrow * 72 + kt * 16 + lkof);
        asm volatile("ldmatrix.sync.aligned.m8n8.x4.shared.b16 {%0,%1,%2,%3}, [%4];"
                     : "=r"(a0), "=r"(a1), "=r"(a2), "=r"(a3) : "r"(addr));
#pragma unroll
        for (int nt = 0; nt < 4; nt++) {
            uint2 bb = __ldg(&g_Wfrag2[((kt << 2) + nt) * 32 + lane]);
            asm volatile(
                "mma.sync.aligned.m16n8k16.row.col.f32.f16.f16.f32 "
                "{%0,%1,%2,%3}, {%4,%5,%6,%7}, {%8,%9}, {%0,%1,%2,%3};"
                : "+f"(acc[nt][0]), "+f"(acc[nt][1]), "+f"(acc[nt][2]), "+f"(acc[nt][3])
                : "r"(a0), "r"(a1), "r"(a2), "r"(a3), "r"(bb.x), "r"(bb.y));
        }
    }

    int r0 = node0 + warpRow + g;
    int r1 = r0 + 8;
#pragma unroll
    for (int nt = 0; nt < 4; nt++) {
        int c = nt * 8 + tg * 2;
        if (r0 < NN) {
            H2U u; u.h = __floats2half2_rn(acc[nt][0], acc[nt][1]);
            *reinterpret_cast<unsigned*>(g_Y2h + (size_t)r0 * 32 + c) = u.u;
        }
        if (r1 < NN) {
            H2U u; u.h = __floats2half2_rn(acc[nt][2], acc[nt][3]);
            *reinterpret_cast<unsigned*>(g_Y2h + (size_t)r1 * 32 + c) = u.u;
        }
    }
}

// ---------------------------------------------------------------------------
// gather2 + head + softmax.  8 nodes/warp, 4 lanes x 8 halves.
// ---------------------------------------------------------------------------
__global__ void k_gather2_final(const float* __restrict__ b2,
                                const float* __restrict__ Wout,
                                const float* __restrict__ bout,
                                float* __restrict__ out) {
    int gw = (blockIdx.x * 256 + threadIdx.x) >> 5;
    int lane = threadIdx.x & 31;
    int sub = lane >> 2, sl = lane & 3;
    int node = gw * 8 + sub;
    if (node >= NN) return;

    int n = g_deg[node]; if (n > CAP) n = CAP;
    const int* bkt = g_bucket + (size_t)node * CAP;
    __half2 z = __float2half2_rn(0.f);
    __half2 s0[4] = {z, z, z, z}, s1[4] = {z, z, z, z};
    __half2 s2[4] = {z, z, z, z}, s3[4] = {z, z, z, z};

    int j = 0;
    for (; j + 4 <= n; j += 4) {
        int4 idx = *reinterpret_cast<const int4*>(bkt + j);
        hacc(s0, *reinterpret_cast<const uint4*>(g_Y2h + (size_t)idx.x * 32 + sl * 8));
        hacc(s1, *reinterpret_cast<const uint4*>(g_Y2h + (size_t)idx.y * 32 + sl * 8));
        hacc(s2, *reinterpret_cast<const uint4*>(g_Y2h + (size_t)idx.z * 32 + sl * 8));
        hacc(s3, *reinterpret_cast<const uint4*>(g_Y2h + (size_t)idx.w * 32 + sl * 8));
    }
    for (; j < n; j++)
        hacc(s0, *reinterpret_cast<const uint4*>(g_Y2h + (size_t)bkt[j] * 32 + sl * 8));

    float4 bL = __ldg(reinterpret_cast<const float4*>(b2 + sl * 8));
    float4 bH = __ldg(reinterpret_cast<const float4*>(b2 + sl * 8 + 4));
    float h[8];
#pragma unroll
    for (int q = 0; q < 4; q++) {
        float2 f  = __half22float2(s0[q]);
        float2 t1 = __half22float2(s1[q]);
        float2 t2 = __half22float2(s2[q]);
        float2 t3 = __half22float2(s3[q]);
        h[q * 2]     = f.x + t1.x + t2.x + t3.x;
        h[q * 2 + 1] = f.y + t1.y + t2.y + t3.y;
    }
    h[0] += bL.x; h[1] += bL.y; h[2] += bL.z; h[3] += bL.w;
    h[4] += bH.x; h[5] += bH.y; h[6] += bH.z; h[7] += bH.w;

    float lg[4];
#pragma unroll
    for (int c = 0; c < 4; c++) {
        float ps = 0.f;
#pragma unroll
        for (int k = 0; k < 8; k++)
            ps = fmaf(h[k], __ldg(Wout + (sl * 8 + k) * 4 + c), ps);
        ps += __shfl_xor_sync(0xffffffffu, ps, 1);
        ps += __shfl_xor_sync(0xffffffffu, ps, 2);
        lg[c] = ps + __ldg(bout + c);
    }

    float m = fmaxf(fmaxf(lg[0], lg[1]), fmaxf(lg[2], lg[3]));
    float e0 = __expf(lg[0] - m);
    float e1 = __expf(lg[1] - m);
    float e2 = __expf(lg[2] - m);
    float e3 = __expf(lg[3] - m);
    float inv = 1.0f / (e0 + e1 + e2 + e3);
    if (sl == 0)
        *reinterpret_cast<float4*>(out + (size_t)node * 4) =
            make_float4(e0 * inv, e1 * inv, e2 * inv, e3 * inv);
}

// ---------------------------------------------------------------------------
// Launch.  Inputs: x, src, dst, w1, Wd1, b1, w2, Wd2, b2, Wout, bout
// Forked topology (captured as a DAG):
//   main:  wfrag -> dense1 ----\
//   side:  zero  -> fill  ------+--> gather1 -> dense2 -> gather2_final
// ---------------------------------------------------------------------------
extern "C" void kernel_launch(void* const* d_in, const int* in_sizes, int n_in,
                              void* d_out, int out_size) {
    const float* x    = (const float*)d_in[0];
    const int*   src  = (const int*)  d_in[1];
    const int*   dst  = (const int*)  d_in[2];
    const float* w1   = (const float*)d_in[3];
    const float* Wd1  = (const float*)d_in[4];
    const float* b1   = (const float*)d_in[5];
    const float* w2   = (const float*)d_in[6];
    const float* Wd2  = (const float*)d_in[7];
    const float* b2   = (const float*)d_in[8];
    const float* Wout = (const float*)d_in[9];
    const float* bout = (const float*)d_in[10];
    float* out = (float*)d_out;

    static cudaStream_t s2 = nullptr;
    static cudaEvent_t  e0 = nullptr, e1 = nullptr;
    if (s2 == nullptr) {
        cudaStreamCreateWithFlags(&s2, cudaStreamNonBlocking);
        cudaEventCreateWithFlags(&e0, cudaEventDisableTiming);
        cudaEventCreateWithFlags(&e1, cudaEventDisableTiming);
    }

    // fork: side stream builds adjacency while main stream does dense1
    cudaEventRecord(e0, 0);
    cudaStreamWaitEvent(s2, e0, 0);
    k_zero<<<196, 256, 0, s2>>>();
    k_fill<<<586, 256, 0, s2>>>(src, dst);
    cudaEventRecord(e1, s2);

    k_wfrag<<<4, 256>>>(w1, Wd1, w2, Wd2);
    k_dense1<<<391, 256>>>(x);

    // join: gather1 needs both dense1 (Y1) and fill (buckets)
    cudaStreamWaitEvent(0, e1, 0);
    k_gather1<<<1563, 256>>>(b1);
    k_dense2<<<391, 256>>>();
    k_gather2_final<<<782, 256>>>(b2, Wout, bout, out);
}

// round 11
// speedup vs baseline: 1.1792x; 1.0448x over previous
#include <cuda_runtime.h>
#include <cuda_fp16.h>

#define NN 50000
#define NE 600000
#define CAP 64            // bucket capacity per node (max degree ~28)

// ---------------- scratch (__device__ globals) -----------------------------
__device__ __half g_Y1h[NN * 64];    // fp16: x @ (diag(w1) Wd1)
__device__ __half g_h1h[NN * 64];    // fp16: A @ Y1 + b1
__device__ __half g_Y2h[NN * 32];    // fp16: h1 @ (diag(w2) Wd2)
__device__ int    g_deg[NN];
__device__ int    g_bucket[NN * CAP];
__device__ uint2  g_Wfrag1[8 * 8 * 32];   // dense1 B fragments [kt][nt][lane]
__device__ uint2  g_Wfrag2[4 * 4 * 32];   // dense2 B fragments [kt][nt][lane]

__device__ __forceinline__ unsigned s2u(const void* p) {
    return (unsigned)__cvta_generic_to_shared(p);
}
union H2U { __half2 h; unsigned u; };

// ---------------------------------------------------------------------------
__global__ void k_zero() {
    int i = blockIdx.x * 256 + threadIdx.x;
    if (i < NN) g_deg[i] = 0;
}

// ---------------------------------------------------------------------------
// k_wfrag: build pre-folded fp16 MMA B-fragments for both dense layers.
// ---------------------------------------------------------------------------
__global__ void k_wfrag(const float* __restrict__ w1, const float* __restrict__ Wd1,
                        const float* __restrict__ w2, const float* __restrict__ Wd2) {
    int tid2 = blockIdx.x * 256 + threadIdx.x;     // 0..1023
    for (int i = tid2; i < 2048; i += 1024) {
        int lane = i & 31, nt = (i >> 5) & 7, kt = i >> 8;
        int g = lane >> 2, tg = lane & 3;
        int n = nt * 8 + g, k0 = kt * 16 + tg * 2;
        float a0 = Wd1[(k0    ) * 64 + n] * w1[k0    ];
        float a1 = Wd1[(k0 + 1) * 64 + n] * w1[k0 + 1];
        float a2 = Wd1[(k0 + 8) * 64 + n] * w1[k0 + 8];
        float a3 = Wd1[(k0 + 9) * 64 + n] * w1[k0 + 9];
        H2U u0, u1;
        u0.h = __floats2half2_rn(a0, a1);
        u1.h = __floats2half2_rn(a2, a3);
        g_Wfrag1[i] = make_uint2(u0.u, u1.u);
    }
    for (int i = tid2; i < 512; i += 1024) {
        int lane = i & 31, nt = (i >> 5) & 3, kt = i >> 7;
        int g = lane >> 2, tg = lane & 3;
        int n = nt * 8 + g, k0 = kt * 16 + tg * 2;
        float a0 = Wd2[(k0    ) * 32 + n] * w2[k0    ];
        float a1 = Wd2[(k0 + 1) * 32 + n] * w2[k0 + 1];
        float a2 = Wd2[(k0 + 8) * 32 + n] * w2[k0 + 8];
        float a3 = Wd2[(k0 + 9) * 32 + n] * w2[k0 + 9];
        H2U u0, u1;
        u0.h = __floats2half2_rn(a0, a1);
        u1.h = __floats2half2_rn(a2, a3);
        g_Wfrag2[i] = make_uint2(u0.u, u1.u);
    }
}

// ---------------------------------------------------------------------------
// k_fill: one-pass adjacency build. deg doubles as cursor.
// ---------------------------------------------------------------------------
__global__ void k_fill(const int* __restrict__ src, const int* __restrict__ dst) {
    int i = blockIdx.x * 256 + threadIdx.x;
    if (i < NE / 4) {
        int4 s = reinterpret_cast<const int4*>(src)[i];
        int4 d = reinterpret_cast<const int4*>(dst)[i];
        int p;
        p = atomicAdd(&g_deg[d.x], 1); if (p < CAP) g_bucket[d.x * CAP + p] = s.x;
        p = atomicAdd(&g_deg[d.y], 1); if (p < CAP) g_bucket[d.y * CAP + p] = s.y;
        p = atomicAdd(&g_deg[d.z], 1); if (p < CAP) g_bucket[d.z * CAP + p] = s.z;
        p = atomicAdd(&g_deg[d.w], 1); if (p < CAP) g_bucket[d.w * CAP + p] = s.w;
    }
}

// ---------------------------------------------------------------------------
// dense1: Y1 = x @ (diag(w1) Wd1)  (K=128 -> N=64), HMMA, 64-node tiles.
// 782 blocks for high occupancy / DRAM MLP.  8 warps = 4 row-tiles x 2 col-halves.
// ---------------------------------------------------------------------------
__global__ void __launch_bounds__(256)
k_dense1(const float* __restrict__ x) {
    __shared__ __half As[64 * 136];      // 17408 B
    int tid = threadIdx.x;
    int node0 = blockIdx.x * 64;
    for (int i = tid; i < 64 * 32; i += 256) {
        int r = i >> 5, c4 = i & 31;
        float4 v = make_float4(0.f, 0.f, 0.f, 0.f);
        if (node0 + r < NN)
            v = *reinterpret_cast<const float4*>(x + (size_t)(node0 + r) * 128 + c4 * 4);
        H2U u0, u1;
        u0.h = __floats2half2_rn(v.x, v.y);
        u1.h = __floats2half2_rn(v.z, v.w);
        *reinterpret_cast<uint2*>(As + r * 136 + c4 * 4) = make_uint2(u0.u, u1.u);
    }
    __syncthreads();

    int w = tid >> 5, lane = tid & 31, g = lane >> 2, tg = lane & 3;
    int warpRow = (w >> 1) * 16;
    int nthalf  = (w & 1) * 4;           // col-half: nt 0..3 or 4..7
    int lrow = warpRow + (lane & 15);
    int lkof = (lane >> 4) * 8;

    float acc[4][4] = {};
#pragma unroll
    for (int kt = 0; kt < 8; kt++) {
        unsigned a0, a1, a2, a3;
        unsigned addr = s2u(As + lrow * 136 + kt * 16 + lkof);
        asm volatile("ldmatrix.sync.aligned.m8n8.x4.shared.b16 {%0,%1,%2,%3}, [%4];"
                     : "=r"(a0), "=r"(a1), "=r"(a2), "=r"(a3) : "r"(addr));
#pragma unroll
        for (int nt = 0; nt < 4; nt++) {
            uint2 bb = __ldg(&g_Wfrag1[((kt << 3) + nthalf + nt) * 32 + lane]);
            asm volatile(
                "mma.sync.aligned.m16n8k16.row.col.f32.f16.f16.f32 "
                "{%0,%1,%2,%3}, {%4,%5,%6,%7}, {%8,%9}, {%0,%1,%2,%3};"
                : "+f"(acc[nt][0]), "+f"(acc[nt][1]), "+f"(acc[nt][2]), "+f"(acc[nt][3])
                : "r"(a0), "r"(a1), "r"(a2), "r"(a3), "r"(bb.x), "r"(bb.y));
        }
    }

    int r0 = node0 + warpRow + g;
    int r1 = r0 + 8;
#pragma unroll
    for (int nt = 0; nt < 4; nt++) {
        int c = (nthalf + nt) * 8 + tg * 2;
        if (r0 < NN) {
            H2U u; u.h = __floats2half2_rn(acc[nt][0], acc[nt][1]);
            *reinterpret_cast<unsigned*>(g_Y1h + (size_t)r0 * 64 + c) = u.u;
        }
        if (r1 < NN) {
            H2U u; u.h = __floats2half2_rn(acc[nt][2], acc[nt][3]);
            *reinterpret_cast<unsigned*>(g_Y1h + (size_t)r1 * 64 + c) = u.u;
        }
    }
}

// ---------------------------------------------------------------------------
// half2 accumulation helper
// ---------------------------------------------------------------------------
__device__ __forceinline__ void hacc(__half2 a[4], uint4 v) {
    __half2* h = reinterpret_cast<__half2*>(&v);
    a[0] = __hadd2(a[0], h[0]);
    a[1] = __hadd2(a[1], h[1]);
    a[2] = __hadd2(a[2], h[2]);
    a[3] = __hadd2(a[3], h[3]);
}

// ---------------------------------------------------------------------------
// gather1: h1 = A@Y1 + b1, fp16 out. 4 nodes/warp, 8 lanes x 8 halves.
// ---------------------------------------------------------------------------
__global__ void __launch_bounds__(256)
k_gather1(const float* __restrict__ b1) {
    int gw = (blockIdx.x * 256 + threadIdx.x) >> 5;
    int lane = threadIdx.x & 31;
    int sub = lane >> 3, sl = lane & 7;
    int node = gw * 4 + sub;
    if (node >= NN) return;

    int n = g_deg[node]; if (n > CAP) n = CAP;
    const int* bkt = g_bucket + (size_t)node * CAP;
    __half2 z = __float2half2_rn(0.f);
    __half2 s0[4] = {z, z, z, z}, s1[4] = {z, z, z, z};
    __half2 s2[4] = {z, z, z, z}, s3[4] = {z, z, z, z};

    int j = 0;
    for (; j + 4 <= n; j += 4) {
        int4 idx = *reinterpret_cast<const int4*>(bkt + j);
        hacc(s0, *reinterpret_cast<const uint4*>(g_Y1h + (size_t)idx.x * 64 + sl * 8));
        hacc(s1, *reinterpret_cast<const uint4*>(g_Y1h + (size_t)idx.y * 64 + sl * 8));
        hacc(s2, *reinterpret_cast<const uint4*>(g_Y1h + (size_t)idx.z * 64 + sl * 8));
        hacc(s3, *reinterpret_cast<const uint4*>(g_Y1h + (size_t)idx.w * 64 + sl * 8));
    }
    for (; j < n; j++)
        hacc(s0, *reinterpret_cast<const uint4*>(g_Y1h + (size_t)bkt[j] * 64 + sl * 8));

    float4 bL = __ldg(reinterpret_cast<const float4*>(b1 + sl * 8));
    float4 bH = __ldg(reinterpret_cast<const float4*>(b1 + sl * 8 + 4));
    float2 f0, f1, f2, f3;
    f0 = __half22float2(s0[0]); { float2 t = __half22float2(s1[0]); f0.x += t.x; f0.y += t.y; }
    { float2 t = __half22float2(s2[0]); f0.x += t.x; f0.y += t.y; }
    { float2 t = __half22float2(s3[0]); f0.x += t.x; f0.y += t.y; }
    f1 = __half22float2(s0[1]); { float2 t = __half22float2(s1[1]); f1.x += t.x; f1.y += t.y; }
    { float2 t = __half22float2(s2[1]); f1.x += t.x; f1.y += t.y; }
    { float2 t = __half22float2(s3[1]); f1.x += t.x; f1.y += t.y; }
    f2 = __half22float2(s0[2]); { float2 t = __half22float2(s1[2]); f2.x += t.x; f2.y += t.y; }
    { float2 t = __half22float2(s2[2]); f2.x += t.x; f2.y += t.y; }
    { float2 t = __half22float2(s3[2]); f2.x += t.x; f2.y += t.y; }
    f3 = __half22float2(s0[3]); { float2 t = __half22float2(s1[3]); f3.x += t.x; f3.y += t.y; }
    { float2 t = __half22float2(s2[3]); f3.x += t.x; f3.y += t.y; }
    { float2 t = __half22float2(s3[3]); f3.x += t.x; f3.y += t.y; }

    H2U p0, p1, p2, p3;
    p0.h = __floats2half2_rn(f0.x + bL.x, f0.y + bL.y);
    p1.h = __floats2half2_rn(f1.x + bL.z, f1.y + bL.w);
    p2.h = __floats2half2_rn(f2.x + bH.x, f2.y + bH.y);
    p3.h = __floats2half2_rn(f3.x + bH.z, f3.y + bH.w);
    *reinterpret_cast<uint4*>(g_h1h + (size_t)node * 64 + sl * 8) =
        make_uint4(p0.u, p1.u, p2.u, p3.u);
}

// ---------------------------------------------------------------------------
// dense2: Y2 = h1 @ (diag(w2) Wd2)  (K=64 -> N=32), HMMA, 128-node tiles.
// ---------------------------------------------------------------------------
__global__ void __launch_bounds__(256)
k_dense2() {
    __shared__ __half As[128 * 72];      // 18432 B
    int tid = threadIdx.x;
    int node0 = blockIdx.x * 128;
    for (int i = tid; i < 128 * 8; i += 256) {
        int r = i >> 3, q = i & 7;
        uint4 v = make_uint4(0u, 0u, 0u, 0u);
        if (node0 + r < NN)
            v = *reinterpret_cast<const uint4*>(g_h1h + (size_t)(node0 + r) * 64 + q * 8);
        *reinterpret_cast<uint4*>(As + r * 72 + q * 8) = v;
    }
    __syncthreads();

    int w = tid >> 5, lane = tid & 31, g = lane >> 2, tg = lane & 3;
    int warpRow = w * 16;
    int lrow = warpRow + (lane & 15);
    int lkof = (lane >> 4) * 8;

    float acc[4][4] = {};
#pragma unroll
    for (int kt = 0; kt < 4; kt++) {
        unsigned a0, a1, a2, a3;
        unsigned addr = s2u(As + lrow * 72 + kt * 16 + lkof);
        asm volatile("ldmatrix.sync.aligned.m8n8.x4.shared.b16 {%0,%1,%2,%3}, [%4];"
                     : "=r"(a0), "=r"(a1), "=r"(a2), "=r"(a3) : "r"(addr));
#pragma unroll
        for (int nt = 0; nt < 4; nt++) {
            uint2 bb = __ldg(&g_Wfrag2[((kt << 2) + nt) * 32 + lane]);
            asm volatile(
                "mma.sync.aligned.m16n8k16.row.col.f32.f16.f16.f32 "
                "{%0,%1,%2,%3}, {%4,%5,%6,%7}, {%8,%9}, {%0,%1,%2,%3};"
                : "+f"(acc[nt][0]), "+f"(acc[nt][1]), "+f"(acc[nt][2]), "+f"(acc[nt][3])
                : "r"(a0), "r"(a1), "r"(a2), "r"(a3), "r"(bb.x), "r"(bb.y));
        }
    }

    int r0 = node0 + warpRow + g;
    int r1 = r0 + 8;
#pragma unroll
    for (int nt = 0; nt < 4; nt++) {
        int c = nt * 8 + tg * 2;
        if (r0 < NN) {
            H2U u; u.h = __floats2half2_rn(acc[nt][0], acc[nt][1]);
            *reinterpret_cast<unsigned*>(g_Y2h + (size_t)r0 * 32 + c) = u.u;
        }
        if (r1 < NN) {
            H2U u; u.h = __floats2half2_rn(acc[nt][2], acc[nt][3]);
            *reinterpret_cast<unsigned*>(g_Y2h + (size_t)r1 * 32 + c) = u.u;
        }
    }
}

// ---------------------------------------------------------------------------
// gather2 + head + softmax.  8 nodes/warp, 4 lanes x 8 halves.
// ---------------------------------------------------------------------------
__global__ void __launch_bounds__(256)
k_gather2_final(const float* __restrict__ b2,
                const float* __restrict__ Wout,
                const float* __restrict__ bout,
                float* __restrict__ out) {
    int gw = (blockIdx.x * 256 + threadIdx.x) >> 5;
    int lane = threadIdx.x & 31;
    int sub = lane >> 2, sl = lane & 3;
    int node = gw * 8 + sub;
    if (node >= NN) return;

    int n = g_deg[node]; if (n > CAP) n = CAP;
    const int* bkt = g_bucket + (size_t)node * CAP;
    __half2 z = __float2half2_rn(0.f);
    __half2 s0[4] = {z, z, z, z}, s1[4] = {z, z, z, z};
    __half2 s2[4] = {z, z, z, z}, s3[4] = {z, z, z, z};

    int j = 0;
    for (; j + 4 <= n; j += 4) {
        int4 idx = *reinterpret_cast<const int4*>(bkt + j);
        hacc(s0, *reinterpret_cast<const uint4*>(g_Y2h + (size_t)idx.x * 32 + sl * 8));
        hacc(s1, *reinterpret_cast<const uint4*>(g_Y2h + (size_t)idx.y * 32 + sl * 8));
        hacc(s2, *reinterpret_cast<const uint4*>(g_Y2h + (size_t)idx.z * 32 + sl * 8));
        hacc(s3, *reinterpret_cast<const uint4*>(g_Y2h + (size_t)idx.w * 32 + sl * 8));
    }
    for (; j < n; j++)
        hacc(s0, *reinterpret_cast<const uint4*>(g_Y2h + (size_t)bkt[j] * 32 + sl * 8));

    float4 bL = __ldg(reinterpret_cast<const float4*>(b2 + sl * 8));
    float4 bH = __ldg(reinterpret_cast<const float4*>(b2 + sl * 8 + 4));
    float h[8];
#pragma unroll
    for (int q = 0; q < 4; q++) {
        float2 f  = __half22float2(s0[q]);
        float2 t1 = __half22float2(s1[q]);
        float2 t2 = __half22float2(s2[q]);
        float2 t3 = __half22float2(s3[q]);
        h[q * 2]     = f.x + t1.x + t2.x + t3.x;
        h[q * 2 + 1] = f.y + t1.y + t2.y + t3.y;
    }
    h[0] += bL.x; h[1] += bL.y; h[2] += bL.z; h[3] += bL.w;
    h[4] += bH.x; h[5] += bH.y; h[6] += bH.z; h[7] += bH.w;

    float lg[4];
#pragma unroll
    for (int c = 0; c < 4; c++) {
        float ps = 0.f;
#pragma unroll
        for (int k = 0; k < 8; k++)
            ps = fmaf(h[k], __ldg(Wout + (sl * 8 + k) * 4 + c), ps);
        ps += __shfl_xor_sync(0xffffffffu, ps, 1);
        ps += __shfl_xor_sync(0xffffffffu, ps, 2);
        lg[c] = ps + __ldg(bout + c);
    }

    float m = fmaxf(fmaxf(lg[0], lg[1]), fmaxf(lg[2], lg[3]));
    float e0 = __expf(lg[0] - m);
    float e1 = __expf(lg[1] - m);
    float e2 = __expf(lg[2] - m);
    float e3 = __expf(lg[3] - m);
    float inv = 1.0f / (e0 + e1 + e2 + e3);
    if (sl == 0)
        *reinterpret_cast<float4*>(out + (size_t)node * 4) =
            make_float4(e0 * inv, e1 * inv, e2 * inv, e3 * inv);
}

// ---------------------------------------------------------------------------
// Launch.  Inputs: x, src, dst, w1, Wd1, b1, w2, Wd2, b2, Wout, bout
// Forked topology (captured as a DAG):
//   main:  wfrag -> dense1 ----\
//   side:  zero  -> fill  ------+--> gather1 -> dense2 -> gather2_final
// ---------------------------------------------------------------------------
extern "C" void kernel_launch(void* const* d_in, const int* in_sizes, int n_in,
                              void* d_out, int out_size) {
    const float* x    = (const float*)d_in[0];
    const int*   src  = (const int*)  d_in[1];
    const int*   dst  = (const int*)  d_in[2];
    const float* w1   = (const float*)d_in[3];
    const float* Wd1  = (const float*)d_in[4];
    const float* b1   = (const float*)d_in[5];
    const float* w2   = (const float*)d_in[6];
    const float* Wd2  = (const float*)d_in[7];
    const float* b2   = (const float*)d_in[8];
    const float* Wout = (const float*)d_in[9];
    const float* bout = (const float*)d_in[10];
    float* out = (float*)d_out;

    static cudaStream_t s2 = nullptr;
    static cudaEvent_t  e0 = nullptr, e1 = nullptr;
    if (s2 == nullptr) {
        cudaStreamCreateWithFlags(&s2, cudaStreamNonBlocking);
        cudaEventCreateWithFlags(&e0, cudaEventDisableTiming);
        cudaEventCreateWithFlags(&e1, cudaEventDisableTiming);
    }

    // fork: side stream builds adjacency while main stream does dense1
    cudaEventRecord(e0, 0);
    cudaStreamWaitEvent(s2, e0, 0);
    k_zero<<<196, 256, 0, s2>>>();
    k_fill<<<586, 256, 0, s2>>>(src, dst);
    cudaEventRecord(e1, s2);

    k_wfrag<<<4, 256>>>(w1, Wd1, w2, Wd2);
    k_dense1<<<782, 256>>>(x);

    // join: gather1 needs both dense1 (Y1) and fill (buckets)
    cudaStreamWaitEvent(0, e1, 0);
    k_gather1<<<1563, 256>>>(b1);
    k_dense2<<<391, 256>>>();
    k_gather2_final<<<782, 256>>>(b2, Wout, bout, out);
}